// round 10
// baseline (speedup 1.0000x reference)
#include <cuda_runtime.h>
#include <cuda_bf16.h>

#define T_DIM 16384
#define H_DIM 4096
#define EPS 1e-5f

// Scratch (allocation-free rule: __device__ globals). 256 MB each.
__device__ float g_y[(size_t)T_DIM * H_DIM];
__device__ float g_r[(size_t)T_DIM * H_DIM];

// ---------------------------------------------------------------------------
// RMSNorm: one block per row, 256 threads, 16 floats/thread kept in registers.
// RELU_IN applies relu to the input before the norm (first norm's input is
// relu(x)).
// ---------------------------------------------------------------------------
template<bool RELU_IN>
__global__ void __launch_bounds__(256) rmsnorm_kernel(
    const float* __restrict__ in, const float* __restrict__ g,
    float* __restrict__ out)
{
    const int row = blockIdx.x;
    const float4* inp  = reinterpret_cast<const float4*>(in + (size_t)row * H_DIM);
    float4*       outp = reinterpret_cast<float4*>(out + (size_t)row * H_DIM);
    const float4* gp   = reinterpret_cast<const float4*>(g);

    float4 v[4];
    float ssq = 0.f;
    #pragma unroll
    for (int i = 0; i < 4; i++) {
        float4 t = inp[threadIdx.x + i * 256];
        if (RELU_IN) {
            t.x = fmaxf(t.x, 0.f); t.y = fmaxf(t.y, 0.f);
            t.z = fmaxf(t.z, 0.f); t.w = fmaxf(t.w, 0.f);
        }
        v[i] = t;
        ssq += t.x * t.x + t.y * t.y + t.z * t.z + t.w * t.w;
    }

    __shared__ float red[8];
    #pragma unroll
    for (int o = 16; o > 0; o >>= 1) ssq += __shfl_xor_sync(0xffffffffu, ssq, o);
    const int wid = threadIdx.x >> 5, lid = threadIdx.x & 31;
    if (lid == 0) red[wid] = ssq;
    __syncthreads();
    if (wid == 0) {
        float s = (lid < 8) ? red[lid] : 0.f;
        #pragma unroll
        for (int o = 4; o > 0; o >>= 1) s += __shfl_xor_sync(0xffffffffu, s, o);
        if (lid == 0) red[0] = rsqrtf(s * (1.0f / H_DIM) + EPS);
    }
    __syncthreads();
    const float rs = red[0];

    #pragma unroll
    for (int i = 0; i < 4; i++) {
        float4 gg = gp[threadIdx.x + i * 256];
        float4 t = v[i];
        t.x *= rs * gg.x; t.y *= rs * gg.y; t.z *= rs * gg.z; t.w *= rs * gg.w;
        outp[threadIdx.x + i * 256] = t;
    }
}

// ---------------------------------------------------------------------------
// SGEMM C = A @ B + addend, fused epilogue.
//   MODE 0: addend = relu(addsrc[idx])   (addsrc = x; C = fresh resid buffer)
//   MODE 1: addend = addsrc[idx]         (addsrc == C: in-place resid update;
//                                         each element read once, written once
//                                         by the same thread -> safe)
// Tile: 128x128 per block, BK=8, 8x8 per thread, 256 threads, 2 blocks/SM.
// Register prefetch of next global tiles to hide LDG latency behind the
// 512-FFMA-per-warp compute body.
// NOTE: no __restrict__ on addsrc/C (they alias in MODE 1).
// ---------------------------------------------------------------------------
template<int MODE>
__global__ void __launch_bounds__(256, 2) gemm_add_kernel(
    const float* __restrict__ A, const float* __restrict__ B,
    const float* addsrc, float* C)
{
    __shared__ float As[8][128];
    __shared__ float Bs[8][128];

    const int tid = threadIdx.x;
    const int tx = tid & 15;        // output col group (0..15)
    const int ty = tid >> 4;        // output row group (0..15)

    const int rowBase = blockIdx.y * 128;
    const int colBase = blockIdx.x * 128;

    // A tile load mapping: 128 rows x 8 k, one float4 per thread
    const int arow = tid >> 1;          // 0..127
    const int acol = (tid & 1) * 4;     // 0 or 4
    // B tile load mapping: 8 k-rows x 128 cols, one float4 per thread
    const int brow = tid >> 5;          // 0..7
    const int bcol = (tid & 31) * 4;    // 0..124

    const float* Ag = A + (size_t)(rowBase + arow) * H_DIM + acol;
    const float* Bg = B + (size_t)brow * H_DIM + colBase + bcol;

    float acc[8][8];
    #pragma unroll
    for (int i = 0; i < 8; i++)
        #pragma unroll
        for (int j = 0; j < 8; j++) acc[i][j] = 0.f;

    // prefetch first tiles
    float4 a4 = *reinterpret_cast<const float4*>(Ag);
    float4 b4 = *reinterpret_cast<const float4*>(Bg);

    for (int k0 = 0; k0 < H_DIM; k0 += 8) {
        As[acol + 0][arow] = a4.x;
        As[acol + 1][arow] = a4.y;
        As[acol + 2][arow] = a4.z;
        As[acol + 3][arow] = a4.w;
        *reinterpret_cast<float4*>(&Bs[brow][bcol]) = b4;
        __syncthreads();

        if (k0 + 8 < H_DIM) {   // prefetch next tiles while computing
            a4 = *reinterpret_cast<const float4*>(Ag + k0 + 8);
            b4 = *reinterpret_cast<const float4*>(Bg + (size_t)(k0 + 8) * H_DIM);
        }

        #pragma unroll
        for (int kk = 0; kk < 8; kk++) {
            float a[8], b[8];
            *reinterpret_cast<float4*>(&a[0]) = *reinterpret_cast<float4*>(&As[kk][ty * 8]);
            *reinterpret_cast<float4*>(&a[4]) = *reinterpret_cast<float4*>(&As[kk][ty * 8 + 4]);
            *reinterpret_cast<float4*>(&b[0]) = *reinterpret_cast<float4*>(&Bs[kk][tx * 8]);
            *reinterpret_cast<float4*>(&b[4]) = *reinterpret_cast<float4*>(&Bs[kk][tx * 8 + 4]);
            #pragma unroll
            for (int i = 0; i < 8; i++)
                #pragma unroll
                for (int j = 0; j < 8; j++)
                    acc[i][j] = fmaf(a[i], b[j], acc[i][j]);
        }
        __syncthreads();
    }

    // fused epilogue
    #pragma unroll
    for (int i = 0; i < 8; i++) {
        const int row = rowBase + ty * 8 + i;
        const size_t base = (size_t)row * H_DIM + colBase + tx * 8;
        #pragma unroll
        for (int j2 = 0; j2 < 2; j2++) {
            float4 add = *reinterpret_cast<const float4*>(addsrc + base + j2 * 4);
            if (MODE == 0) {
                add.x = fmaxf(add.x, 0.f); add.y = fmaxf(add.y, 0.f);
                add.z = fmaxf(add.z, 0.f); add.w = fmaxf(add.w, 0.f);
            }
            float4 o;
            o.x = acc[i][j2 * 4 + 0] + add.x;
            o.y = acc[i][j2 * 4 + 1] + add.y;
            o.z = acc[i][j2 * 4 + 2] + add.z;
            o.w = acc[i][j2 * 4 + 3] + add.w;
            *reinterpret_cast<float4*>(C + base + j2 * 4) = o;
        }
    }
}

// ---------------------------------------------------------------------------
// Pipeline:
//   y = rmsnorm(relu(x), g0)
//   r = y @ w0 + relu(x)
//   y = rmsnorm(r, g1)
//   r = y @ w1 + r        (in-place)
//   out = rmsnorm(r, g2)
// ---------------------------------------------------------------------------
extern "C" void kernel_launch(void* const* d_in, const int* in_sizes, int n_in,
                              void* d_out, int out_size) {
    const float* x  = (const float*)d_in[0];
    const float* g0 = (const float*)d_in[1];
    const float* g1 = (const float*)d_in[2];
    const float* g2 = (const float*)d_in[3];
    const float* w0 = (const float*)d_in[4];
    const float* w1 = (const float*)d_in[5];
    float* out = (float*)d_out;

    float *y = nullptr, *r = nullptr;
    cudaGetSymbolAddress((void**)&y, g_y);
    cudaGetSymbolAddress((void**)&r, g_r);

    dim3 gridN(T_DIM);
    dim3 gridG(H_DIM / 128, T_DIM / 128);

    rmsnorm_kernel<true ><<<gridN, 256>>>(x, g0, y);
    gemm_add_kernel<0>   <<<gridG, 256>>>(y, w0, x, r);
    rmsnorm_kernel<false><<<gridN, 256>>>(r, g1, y);
    gemm_add_kernel<1>   <<<gridG, 256>>>(y, w1, r, r);
    rmsnorm_kernel<false><<<gridN, 256>>>(r, g2, out);
}

// round 12
// speedup vs baseline: 2.8548x; 2.8548x over previous
#include <cuda_runtime.h>
#include <cuda_bf16.h>
#include <stdint.h>

#define T_DIM 16384
#define H_DIM 4096
#define EPS 1e-5f

// ---------------------------------------------------------------------------
// Scratch (__device__ globals; allocation-free rule)
// ---------------------------------------------------------------------------
__device__ __align__(16) __nv_bfloat16 g_ahi[(size_t)T_DIM * H_DIM];  // 128 MB
__device__ __align__(16) __nv_bfloat16 g_alo[(size_t)T_DIM * H_DIM];  // 128 MB
__device__ __align__(16) float         g_r  [(size_t)T_DIM * H_DIM];  // 256 MB
__device__ __align__(16) __nv_bfloat16 g_bhi[(size_t)H_DIM * H_DIM];  // 32 MB
__device__ __align__(16) __nv_bfloat16 g_blo[(size_t)H_DIM * H_DIM];  // 32 MB

// ---------------------------------------------------------------------------
// PTX helpers — ONLY family-portable instructions (sm_80/75-era): ldmatrix,
// mma.sync bf16, cp.async. NO tcgen05 (rejected by this harness's compute_103
// PTX target).
// ---------------------------------------------------------------------------
__device__ __forceinline__ uint32_t smem_to_u32(const void* p) {
    uint32_t a;
    asm("{ .reg .u64 t; cvta.to.shared.u64 t, %1; cvt.u32.u64 %0, t; }" : "=r"(a) : "l"(p));
    return a;
}
#define CP_ASYNC_16(dst, src) \
    asm volatile("cp.async.cg.shared.global [%0], [%1], 16;" :: "r"(dst), "l"(src))
#define CP_COMMIT() asm volatile("cp.async.commit_group;" ::: "memory")
#define CP_WAIT1()  asm volatile("cp.async.wait_group 1;" ::: "memory")
#define CP_WAIT0()  asm volatile("cp.async.wait_group 0;" ::: "memory")

__device__ __forceinline__ void ldmatrix_x4(uint32_t* r, uint32_t addr) {
    asm volatile("ldmatrix.sync.aligned.m8n8.x4.shared.b16 {%0,%1,%2,%3}, [%4];"
                 : "=r"(r[0]), "=r"(r[1]), "=r"(r[2]), "=r"(r[3]) : "r"(addr));
}
__device__ __forceinline__ void ldmatrix_x2(uint32_t* r, uint32_t addr) {
    asm volatile("ldmatrix.sync.aligned.m8n8.x2.shared.b16 {%0,%1}, [%2];"
                 : "=r"(r[0]), "=r"(r[1]) : "r"(addr));
}
__device__ __forceinline__ void mma_16816(float* c, const uint32_t* a, const uint32_t* b) {
    asm volatile("mma.sync.aligned.m16n8k16.row.col.f32.bf16.bf16.f32 "
                 "{%0,%1,%2,%3}, {%4,%5,%6,%7}, {%8,%9}, {%0,%1,%2,%3};"
                 : "+f"(c[0]), "+f"(c[1]), "+f"(c[2]), "+f"(c[3])
                 : "r"(a[0]), "r"(a[1]), "r"(a[2]), "r"(a[3]), "r"(b[0]), "r"(b[1]));
}

// ---------------------------------------------------------------------------
// RMSNorm -> bf16 hi/lo split (Dekker split feeding the MMA GEMM).
// ---------------------------------------------------------------------------
template<bool RELU_IN>
__global__ void __launch_bounds__(256) rmsnorm_split_kernel(
    const float* __restrict__ in, const float* __restrict__ g,
    __nv_bfloat16* __restrict__ ohi, __nv_bfloat16* __restrict__ olo)
{
    const int row = blockIdx.x;
    const float4* inp = reinterpret_cast<const float4*>(in + (size_t)row * H_DIM);
    const float4* gp  = reinterpret_cast<const float4*>(g);
    uint2* hip = reinterpret_cast<uint2*>(ohi + (size_t)row * H_DIM);
    uint2* lop = reinterpret_cast<uint2*>(olo + (size_t)row * H_DIM);

    float4 v[4];
    float ssq = 0.f;
    #pragma unroll
    for (int i = 0; i < 4; i++) {
        float4 t = inp[threadIdx.x + i * 256];
        if (RELU_IN) {
            t.x = fmaxf(t.x, 0.f); t.y = fmaxf(t.y, 0.f);
            t.z = fmaxf(t.z, 0.f); t.w = fmaxf(t.w, 0.f);
        }
        v[i] = t;
        ssq += t.x * t.x + t.y * t.y + t.z * t.z + t.w * t.w;
    }

    __shared__ float red[8];
    #pragma unroll
    for (int o = 16; o > 0; o >>= 1) ssq += __shfl_xor_sync(0xffffffffu, ssq, o);
    const int wid = threadIdx.x >> 5, lid = threadIdx.x & 31;
    if (lid == 0) red[wid] = ssq;
    __syncthreads();
    if (wid == 0) {
        float s = (lid < 8) ? red[lid] : 0.f;
        #pragma unroll
        for (int o = 4; o > 0; o >>= 1) s += __shfl_xor_sync(0xffffffffu, s, o);
        if (lid == 0) red[0] = rsqrtf(s * (1.0f / H_DIM) + EPS);
    }
    __syncthreads();
    const float rs = red[0];

    #pragma unroll
    for (int i = 0; i < 4; i++) {
        float4 gg = gp[threadIdx.x + i * 256];
        float4 t = v[i];
        t.x *= rs * gg.x; t.y *= rs * gg.y; t.z *= rs * gg.z; t.w *= rs * gg.w;
        __nv_bfloat16 h0 = __float2bfloat16(t.x), h1 = __float2bfloat16(t.y);
        __nv_bfloat16 h2 = __float2bfloat16(t.z), h3 = __float2bfloat16(t.w);
        __nv_bfloat16 l0 = __float2bfloat16(t.x - __bfloat162float(h0));
        __nv_bfloat16 l1 = __float2bfloat16(t.y - __bfloat162float(h1));
        __nv_bfloat16 l2 = __float2bfloat16(t.z - __bfloat162float(h2));
        __nv_bfloat16 l3 = __float2bfloat16(t.w - __bfloat162float(h3));
        uint2 uh, ul;
        uh.x = (uint32_t)__bfloat16_as_ushort(h0) | ((uint32_t)__bfloat16_as_ushort(h1) << 16);
        uh.y = (uint32_t)__bfloat16_as_ushort(h2) | ((uint32_t)__bfloat16_as_ushort(h3) << 16);
        ul.x = (uint32_t)__bfloat16_as_ushort(l0) | ((uint32_t)__bfloat16_as_ushort(l1) << 16);
        ul.y = (uint32_t)__bfloat16_as_ushort(l2) | ((uint32_t)__bfloat16_as_ushort(l3) << 16);
        hip[threadIdx.x + i * 256] = uh;
        lop[threadIdx.x + i * 256] = ul;
    }
}

// Final RMSNorm -> fp32 out
__global__ void __launch_bounds__(256) rmsnorm_f32_kernel(
    const float* __restrict__ in, const float* __restrict__ g, float* __restrict__ out)
{
    const int row = blockIdx.x;
    const float4* inp  = reinterpret_cast<const float4*>(in + (size_t)row * H_DIM);
    float4*       outp = reinterpret_cast<float4*>(out + (size_t)row * H_DIM);
    const float4* gp   = reinterpret_cast<const float4*>(g);

    float4 v[4];
    float ssq = 0.f;
    #pragma unroll
    for (int i = 0; i < 4; i++) {
        float4 t = inp[threadIdx.x + i * 256];
        v[i] = t;
        ssq += t.x * t.x + t.y * t.y + t.z * t.z + t.w * t.w;
    }
    __shared__ float red[8];
    #pragma unroll
    for (int o = 16; o > 0; o >>= 1) ssq += __shfl_xor_sync(0xffffffffu, ssq, o);
    const int wid = threadIdx.x >> 5, lid = threadIdx.x & 31;
    if (lid == 0) red[wid] = ssq;
    __syncthreads();
    if (wid == 0) {
        float s = (lid < 8) ? red[lid] : 0.f;
        #pragma unroll
        for (int o = 4; o > 0; o >>= 1) s += __shfl_xor_sync(0xffffffffu, s, o);
        if (lid == 0) red[0] = rsqrtf(s * (1.0f / H_DIM) + EPS);
    }
    __syncthreads();
    const float rs = red[0];
    #pragma unroll
    for (int i = 0; i < 4; i++) {
        float4 gg = gp[threadIdx.x + i * 256];
        float4 t = v[i];
        t.x *= rs * gg.x; t.y *= rs * gg.y; t.z *= rs * gg.z; t.w *= rs * gg.w;
        outp[threadIdx.x + i * 256] = t;
    }
}

// ---------------------------------------------------------------------------
// Transpose + bf16 hi/lo split: Bt[n][k] = w[k][n] (MMA B operand is K-major
// per-n row == col-major k x n, loadable by ldmatrix without .trans).
// ---------------------------------------------------------------------------
__global__ void __launch_bounds__(256) transpose_split_kernel(
    const float* __restrict__ w, __nv_bfloat16* __restrict__ bhi, __nv_bfloat16* __restrict__ blo)
{
    __shared__ float tile[32][33];
    const int x  = blockIdx.x * 32 + threadIdx.x;   // n
    const int y0 = blockIdx.y * 32 + threadIdx.y;   // k
    #pragma unroll
    for (int j = 0; j < 4; j++)
        tile[threadIdx.y + 8 * j][threadIdx.x] = w[(size_t)(y0 + 8 * j) * H_DIM + x];
    __syncthreads();
    const int xo = blockIdx.y * 32 + threadIdx.x;   // k
    const int yo = blockIdx.x * 32 + threadIdx.y;   // n
    #pragma unroll
    for (int j = 0; j < 4; j++) {
        float v = tile[threadIdx.x][threadIdx.y + 8 * j];
        __nv_bfloat16 h = __float2bfloat16(v);
        __nv_bfloat16 l = __float2bfloat16(v - __bfloat162float(h));
        bhi[(size_t)(yo + 8 * j) * H_DIM + xo] = h;
        blo[(size_t)(yo + 8 * j) * H_DIM + xo] = l;
    }
}

// ---------------------------------------------------------------------------
// mma.sync bf16 GEMM: C[128x128 tile] = A @ Bt^T + addend, 3-pass split
// (hi*hi + hi*lo + lo*hi), fp32 accum in registers.
//   MODE 0: addend = relu(addsrc)
//   MODE 1: addend = addsrc (in-place safe: read+write by same thread)
// 256 threads = 8 warps (4 M x 2 N), warp tile 32x64, BK=64, 3-stage cp.async
// pipeline. Smem rows are 128 B, xor-swizzled (chunk16 ^= row&7) so ldmatrix
// 8-row gathers are bank-conflict-free.
// ---------------------------------------------------------------------------
#define BKK 64
#define NCHUNK (H_DIM / BKK)            // 64
#define MTILE_B 16384                   // 128 rows x 128 B per matrix tile
#define STAGE_B (4 * MTILE_B)           // Ahi, Alo, Bhi, Blo = 64 KB
#define STAGES 3
#define GEMM_SMEM_TOTAL (STAGES * STAGE_B)  // 192 KB

__device__ __forceinline__ void gemm_load_stage(
    uint32_t sbase, int slot, int k0, int tid, int rowBase, int colBase,
    const __nv_bfloat16* Ahi, const __nv_bfloat16* Alo,
    const __nv_bfloat16* Bhi, const __nv_bfloat16* Blo)
{
    const char* gsrc[4];
    gsrc[0] = (const char*)(Ahi + (size_t)rowBase * H_DIM + k0);
    gsrc[1] = (const char*)(Alo + (size_t)rowBase * H_DIM + k0);
    gsrc[2] = (const char*)(Bhi + (size_t)colBase * H_DIM + k0);
    gsrc[3] = (const char*)(Blo + (size_t)colBase * H_DIM + k0);
    const uint32_t stage_base = sbase + slot * STAGE_B;
    #pragma unroll
    for (int t = 0; t < 4; t++) {
        #pragma unroll
        for (int j = 0; j < 4; j++) {           // 1024 16B-chunks / 256 thr
            int idx = j * 256 + tid;
            int r = idx >> 3;                   // tile row 0..127
            int c = idx & 7;                    // 16B chunk 0..7
            const char* src = gsrc[t] + (size_t)r * (H_DIM * 2) + c * 16;
            uint32_t dst = stage_base + t * MTILE_B + r * 128 + ((c ^ (r & 7)) * 16);
            CP_ASYNC_16(dst, src);
        }
    }
}

template<int MODE>
__global__ void __launch_bounds__(256) gemm_mma_kernel(
    const __nv_bfloat16* __restrict__ Ahi, const __nv_bfloat16* __restrict__ Alo,
    const __nv_bfloat16* __restrict__ Bhi, const __nv_bfloat16* __restrict__ Blo,
    const float* addsrc, float* C)
{
    extern __shared__ char smem[];
    const uint32_t sbase = smem_to_u32(smem);
    const int tid  = threadIdx.x;
    const int lane = tid & 31;
    const int wid  = tid >> 5;
    const int warp_m = wid & 3;     // 0..3  (M)
    const int warp_n = wid >> 2;    // 0..1  (N)

    const int colBase = blockIdx.x * 128;
    const int rowBase = blockIdx.y * 128;

    float acc[2][8][4];
    #pragma unroll
    for (int mt = 0; mt < 2; mt++)
        #pragma unroll
        for (int nt = 0; nt < 8; nt++)
            #pragma unroll
            for (int q = 0; q < 4; q++) acc[mt][nt][q] = 0.f;

    // pipeline prologue: stages 0, 1
    gemm_load_stage(sbase, 0, 0,   tid, rowBase, colBase, Ahi, Alo, Bhi, Blo);
    CP_COMMIT();
    gemm_load_stage(sbase, 1, BKK, tid, rowBase, colBase, Ahi, Alo, Bhi, Blo);
    CP_COMMIT();

    for (int i = 0; i < NCHUNK; i++) {
        if (i + 1 < NCHUNK) { CP_WAIT1(); } else { CP_WAIT0(); }
        __syncthreads();
        if (i + 2 < NCHUNK) {
            gemm_load_stage(sbase, (i + 2) % STAGES, (i + 2) * BKK,
                            tid, rowBase, colBase, Ahi, Alo, Bhi, Blo);
            CP_COMMIT();
        }

        const uint32_t st = sbase + (i % STAGES) * STAGE_B;
        #pragma unroll
        for (int ks = 0; ks < 4; ks++) {        // four k16 steps in BK=64
            uint32_t ahi[2][4], alo[2][4], bhi[8][2], blo[8][2];

            // A fragments: ldmatrix.x4; rows m0-15, chunks k0-7 / k8-15
            const int arow0 = warp_m * 32 + (lane & 15);
            const int ac    = ks * 2 + (lane >> 4);
            #pragma unroll
            for (int mt = 0; mt < 2; mt++) {
                const int r = arow0 + mt * 16;
                const uint32_t off = r * 128 + ((ac ^ (r & 7)) * 16);
                ldmatrix_x4(ahi[mt], st + off);
                ldmatrix_x4(alo[mt], st + MTILE_B + off);
            }
            // B fragments: ldmatrix.x2 from Bt[n][k] row-major
            const int brow0 = warp_n * 64 + (lane & 7);
            const int bc    = ks * 2 + ((lane >> 3) & 1);
            #pragma unroll
            for (int nt = 0; nt < 8; nt++) {
                const int r = brow0 + nt * 8;
                const uint32_t off = r * 128 + ((bc ^ (r & 7)) * 16);
                ldmatrix_x2(bhi[nt], st + 2 * MTILE_B + off);
                ldmatrix_x2(blo[nt], st + 3 * MTILE_B + off);
            }
            // 3-pass split accumulation
            #pragma unroll
            for (int mt = 0; mt < 2; mt++)
                #pragma unroll
                for (int nt = 0; nt < 8; nt++) {
                    mma_16816(acc[mt][nt], ahi[mt], bhi[nt]);
                    mma_16816(acc[mt][nt], ahi[mt], blo[nt]);
                    mma_16816(acc[mt][nt], alo[mt], bhi[nt]);
                }
        }
        __syncthreads();
    }

    // Epilogue: acc mapping for m16n8 — c0,c1 at row g, cols 2q+{0,1};
    // c2,c3 at row g+8.
    const int g = lane >> 2, q = lane & 3;
    #pragma unroll
    for (int mt = 0; mt < 2; mt++) {
        #pragma unroll
        for (int nt = 0; nt < 8; nt++) {
            const int row0 = rowBase + warp_m * 32 + mt * 16 + g;
            const int col  = colBase + warp_n * 64 + nt * 8 + q * 2;
            #pragma unroll
            for (int h = 0; h < 2; h++) {
                const size_t idx = (size_t)(row0 + h * 8) * H_DIM + col;
                float2 add = *reinterpret_cast<const float2*>(addsrc + idx);
                if (MODE == 0) {
                    add.x = fmaxf(add.x, 0.f);
                    add.y = fmaxf(add.y, 0.f);
                }
                float2 o;
                o.x = acc[mt][nt][2 * h + 0] + add.x;
                o.y = acc[mt][nt][2 * h + 1] + add.y;
                *reinterpret_cast<float2*>(C + idx) = o;
            }
        }
    }
}

// ---------------------------------------------------------------------------
// Pipeline:
//   (ahi,alo) = split(rmsnorm(relu(x), g0));  (bhi,blo) = transpose_split(w0)
//   r  = mma3pass(a,b) + relu(x)
//   (ahi,alo) = split(rmsnorm(r, g1));        (bhi,blo) = transpose_split(w1)
//   r += mma3pass(a,b)          (in place)
//   out = rmsnorm(r, g2)
// ---------------------------------------------------------------------------
extern "C" void kernel_launch(void* const* d_in, const int* in_sizes, int n_in,
                              void* d_out, int out_size) {
    const float* x  = (const float*)d_in[0];
    const float* g0 = (const float*)d_in[1];
    const float* g1 = (const float*)d_in[2];
    const float* g2 = (const float*)d_in[3];
    const float* w0 = (const float*)d_in[4];
    const float* w1 = (const float*)d_in[5];
    float* out = (float*)d_out;

    __nv_bfloat16 *ahi = nullptr, *alo = nullptr, *bhi = nullptr, *blo = nullptr;
    float* r = nullptr;
    cudaGetSymbolAddress((void**)&ahi, g_ahi);
    cudaGetSymbolAddress((void**)&alo, g_alo);
    cudaGetSymbolAddress((void**)&bhi, g_bhi);
    cudaGetSymbolAddress((void**)&blo, g_blo);
    cudaGetSymbolAddress((void**)&r,   g_r);

    cudaFuncSetAttribute(gemm_mma_kernel<0>, cudaFuncAttributeMaxDynamicSharedMemorySize, GEMM_SMEM_TOTAL);
    cudaFuncSetAttribute(gemm_mma_kernel<1>, cudaFuncAttributeMaxDynamicSharedMemorySize, GEMM_SMEM_TOTAL);

    dim3 gridN(T_DIM);
    dim3 gridT(H_DIM / 32, H_DIM / 32);
    dim3 gridG(H_DIM / 128, T_DIM / 128);
    dim3 blkT(32, 8);

    rmsnorm_split_kernel<true ><<<gridN, 256>>>(x, g0, ahi, alo);
    transpose_split_kernel      <<<gridT, blkT>>>(w0, bhi, blo);
    gemm_mma_kernel<0>          <<<gridG, 256, GEMM_SMEM_TOTAL>>>(ahi, alo, bhi, blo, x, r);
    rmsnorm_split_kernel<false><<<gridN, 256>>>(r, g1, ahi, alo);
    transpose_split_kernel      <<<gridT, blkT>>>(w1, bhi, blo);
    gemm_mma_kernel<1>          <<<gridG, 256, GEMM_SMEM_TOTAL>>>(ahi, alo, bhi, blo, r, r);
    rmsnorm_f32_kernel          <<<gridN, 256>>>(r, g2, out);
}

// round 13
// speedup vs baseline: 3.9169x; 1.3721x over previous
#include <cuda_runtime.h>
#include <cuda_fp16.h>
#include <stdint.h>

#define T_DIM 16384
#define H_DIM 4096
#define EPS 1e-5f

// ---------------------------------------------------------------------------
// Scratch (__device__ globals; allocation-free rule)
// ---------------------------------------------------------------------------
__device__ __align__(16) __half g_a  [(size_t)T_DIM * H_DIM];  // 128 MB (A fp16)
__device__ __align__(16) float  g_r  [(size_t)T_DIM * H_DIM];  // 256 MB
__device__ __align__(16) __half g_bhi[(size_t)H_DIM * H_DIM];  // 32 MB
__device__ __align__(16) __half g_blo[(size_t)H_DIM * H_DIM];  // 32 MB

// ---------------------------------------------------------------------------
// PTX helpers — family-portable only (ldmatrix / mma.sync / cp.async).
// tcgen05 is rejected by this harness's compute_103 PTX stage (R11 finding).
// ---------------------------------------------------------------------------
__device__ __forceinline__ uint32_t smem_to_u32(const void* p) {
    uint32_t a;
    asm("{ .reg .u64 t; cvta.to.shared.u64 t, %1; cvt.u32.u64 %0, t; }" : "=r"(a) : "l"(p));
    return a;
}
#define CP_ASYNC_16(dst, src) \
    asm volatile("cp.async.cg.shared.global [%0], [%1], 16;" :: "r"(dst), "l"(src))
#define CP_COMMIT() asm volatile("cp.async.commit_group;" ::: "memory")
#define CP_WAIT1()  asm volatile("cp.async.wait_group 1;" ::: "memory")
#define CP_WAIT0()  asm volatile("cp.async.wait_group 0;" ::: "memory")

__device__ __forceinline__ void ldmatrix_x4(uint32_t* r, uint32_t addr) {
    asm volatile("ldmatrix.sync.aligned.m8n8.x4.shared.b16 {%0,%1,%2,%3}, [%4];"
                 : "=r"(r[0]), "=r"(r[1]), "=r"(r[2]), "=r"(r[3]) : "r"(addr));
}
// fp16 MMA, fp32 accumulate
__device__ __forceinline__ void mma_16816(float* c, const uint32_t* a, const uint32_t* b) {
    asm volatile("mma.sync.aligned.m16n8k16.row.col.f32.f16.f16.f32 "
                 "{%0,%1,%2,%3}, {%4,%5,%6,%7}, {%8,%9}, {%0,%1,%2,%3};"
                 : "+f"(c[0]), "+f"(c[1]), "+f"(c[2]), "+f"(c[3])
                 : "r"(a[0]), "r"(a[1]), "r"(a[2]), "r"(a[3]), "r"(b[0]), "r"(b[1]));
}

// ---------------------------------------------------------------------------
// RMSNorm -> single fp16 plane (A operand; B carries the exact split).
// ---------------------------------------------------------------------------
template<bool RELU_IN>
__global__ void __launch_bounds__(256) rmsnorm_h_kernel(
    const float* __restrict__ in, const float* __restrict__ g,
    __half* __restrict__ oh)
{
    const int row = blockIdx.x;
    const float4* inp = reinterpret_cast<const float4*>(in + (size_t)row * H_DIM);
    const float4* gp  = reinterpret_cast<const float4*>(g);
    uint2* hp = reinterpret_cast<uint2*>(oh + (size_t)row * H_DIM);

    float4 v[4];
    float ssq = 0.f;
    #pragma unroll
    for (int i = 0; i < 4; i++) {
        float4 t = inp[threadIdx.x + i * 256];
        if (RELU_IN) {
            t.x = fmaxf(t.x, 0.f); t.y = fmaxf(t.y, 0.f);
            t.z = fmaxf(t.z, 0.f); t.w = fmaxf(t.w, 0.f);
        }
        v[i] = t;
        ssq += t.x * t.x + t.y * t.y + t.z * t.z + t.w * t.w;
    }

    __shared__ float red[8];
    #pragma unroll
    for (int o = 16; o > 0; o >>= 1) ssq += __shfl_xor_sync(0xffffffffu, ssq, o);
    const int wid = threadIdx.x >> 5, lid = threadIdx.x & 31;
    if (lid == 0) red[wid] = ssq;
    __syncthreads();
    if (wid == 0) {
        float s = (lid < 8) ? red[lid] : 0.f;
        #pragma unroll
        for (int o = 4; o > 0; o >>= 1) s += __shfl_xor_sync(0xffffffffu, s, o);
        if (lid == 0) red[0] = rsqrtf(s * (1.0f / H_DIM) + EPS);
    }
    __syncthreads();
    const float rs = red[0];

    #pragma unroll
    for (int i = 0; i < 4; i++) {
        float4 gg = gp[threadIdx.x + i * 256];
        float4 t = v[i];
        t.x *= rs * gg.x; t.y *= rs * gg.y; t.z *= rs * gg.z; t.w *= rs * gg.w;
        __half h0 = __float2half_rn(t.x), h1 = __float2half_rn(t.y);
        __half h2 = __float2half_rn(t.z), h3 = __float2half_rn(t.w);
        uint2 uh;
        uh.x = (uint32_t)__half_as_ushort(h0) | ((uint32_t)__half_as_ushort(h1) << 16);
        uh.y = (uint32_t)__half_as_ushort(h2) | ((uint32_t)__half_as_ushort(h3) << 16);
        hp[threadIdx.x + i * 256] = uh;
    }
}

// Final RMSNorm -> fp32 out
__global__ void __launch_bounds__(256) rmsnorm_f32_kernel(
    const float* __restrict__ in, const float* __restrict__ g, float* __restrict__ out)
{
    const int row = blockIdx.x;
    const float4* inp  = reinterpret_cast<const float4*>(in + (size_t)row * H_DIM);
    float4*       outp = reinterpret_cast<float4*>(out + (size_t)row * H_DIM);
    const float4* gp   = reinterpret_cast<const float4*>(g);

    float4 v[4];
    float ssq = 0.f;
    #pragma unroll
    for (int i = 0; i < 4; i++) {
        float4 t = inp[threadIdx.x + i * 256];
        v[i] = t;
        ssq += t.x * t.x + t.y * t.y + t.z * t.z + t.w * t.w;
    }
    __shared__ float red[8];
    #pragma unroll
    for (int o = 16; o > 0; o >>= 1) ssq += __shfl_xor_sync(0xffffffffu, ssq, o);
    const int wid = threadIdx.x >> 5, lid = threadIdx.x & 31;
    if (lid == 0) red[wid] = ssq;
    __syncthreads();
    if (wid == 0) {
        float s = (lid < 8) ? red[lid] : 0.f;
        #pragma unroll
        for (int o = 4; o > 0; o >>= 1) s += __shfl_xor_sync(0xffffffffu, s, o);
        if (lid == 0) red[0] = rsqrtf(s * (1.0f / H_DIM) + EPS);
    }
    __syncthreads();
    const float rs = red[0];
    #pragma unroll
    for (int i = 0; i < 4; i++) {
        float4 gg = gp[threadIdx.x + i * 256];
        float4 t = v[i];
        t.x *= rs * gg.x; t.y *= rs * gg.y; t.z *= rs * gg.z; t.w *= rs * gg.w;
        outp[threadIdx.x + i * 256] = t;
    }
}

// ---------------------------------------------------------------------------
// Transpose + EXACT fp16 Dekker split: Bt[n][k] = w[k][n] = bhi + blo.
// ---------------------------------------------------------------------------
__global__ void __launch_bounds__(256) transpose_split_kernel(
    const float* __restrict__ w, __half* __restrict__ bhi, __half* __restrict__ blo)
{
    __shared__ float tile[32][33];
    const int x  = blockIdx.x * 32 + threadIdx.x;   // n
    const int y0 = blockIdx.y * 32 + threadIdx.y;   // k
    #pragma unroll
    for (int j = 0; j < 4; j++)
        tile[threadIdx.y + 8 * j][threadIdx.x] = w[(size_t)(y0 + 8 * j) * H_DIM + x];
    __syncthreads();
    const int xo = blockIdx.y * 32 + threadIdx.x;   // k
    const int yo = blockIdx.x * 32 + threadIdx.y;   // n
    #pragma unroll
    for (int j = 0; j < 4; j++) {
        float v = tile[threadIdx.x][threadIdx.y + 8 * j];
        __half h = __float2half_rn(v);
        __half l = __float2half_rn(v - __half2float(h));
        bhi[(size_t)(yo + 8 * j) * H_DIM + xo] = h;
        blo[(size_t)(yo + 8 * j) * H_DIM + xo] = l;
    }
}

// ---------------------------------------------------------------------------
// mma.sync fp16 GEMM: C[128x128] = A @ (Bhi + Blo)^T + addend, 2 passes.
// A single fp16 (only error source: A truncation, ~2.8e-4 RMS).
//   MODE 0: addend = relu(addsrc);  MODE 1: addend = addsrc (in-place safe)
// 256 threads = 8 warps (4M x 2N), warp tile 32x64, BK=64, 3-stage cp.async.
// Stage = 3 tiles (A, Bhi, Blo) x 16 KB = 48 KB; smem rows 128 B, xor-swizzled.
// ---------------------------------------------------------------------------
#define BKK 64
#define NCHUNK (H_DIM / BKK)            // 64
#define MTILE_B 16384                   // 128 rows x 128 B
#define STAGE_B (3 * MTILE_B)           // A, Bhi, Blo = 48 KB
#define STAGES 3
#define GEMM_SMEM_TOTAL (STAGES * STAGE_B)  // 144 KB

__device__ __forceinline__ void gemm_load_stage(
    uint32_t sbase, int slot, int k0, int tid, int rowBase, int colBase,
    const __half* A, const __half* Bhi, const __half* Blo)
{
    const char* gsrc[3];
    gsrc[0] = (const char*)(A   + (size_t)rowBase * H_DIM + k0);
    gsrc[1] = (const char*)(Bhi + (size_t)colBase * H_DIM + k0);
    gsrc[2] = (const char*)(Blo + (size_t)colBase * H_DIM + k0);
    const uint32_t stage_base = sbase + slot * STAGE_B;
    #pragma unroll
    for (int t = 0; t < 3; t++) {
        #pragma unroll
        for (int j = 0; j < 4; j++) {           // 1024 16B chunks / 256 thr
            int idx = j * 256 + tid;
            int r = idx >> 3;                   // tile row 0..127
            int c = idx & 7;                    // 16B chunk 0..7
            const char* src = gsrc[t] + (size_t)r * (H_DIM * 2) + c * 16;
            uint32_t dst = stage_base + t * MTILE_B + r * 128 + ((c ^ (r & 7)) * 16);
            CP_ASYNC_16(dst, src);
        }
    }
}

template<int MODE>
__global__ void __launch_bounds__(256) gemm_mma_kernel(
    const __half* __restrict__ A, const __half* __restrict__ Bhi,
    const __half* __restrict__ Blo, const float* addsrc, float* C)
{
    extern __shared__ char smem[];
    const uint32_t sbase = smem_to_u32(smem);
    const int tid  = threadIdx.x;
    const int lane = tid & 31;
    const int wid  = tid >> 5;
    const int warp_m = wid & 3;     // 0..3  (M)
    const int warp_n = wid >> 2;    // 0..1  (N)

    const int colBase = blockIdx.x * 128;
    const int rowBase = blockIdx.y * 128;

    float acc[2][8][4];
    #pragma unroll
    for (int mt = 0; mt < 2; mt++)
        #pragma unroll
        for (int nt = 0; nt < 8; nt++)
            #pragma unroll
            for (int q = 0; q < 4; q++) acc[mt][nt][q] = 0.f;

    gemm_load_stage(sbase, 0, 0,   tid, rowBase, colBase, A, Bhi, Blo);
    CP_COMMIT();
    gemm_load_stage(sbase, 1, BKK, tid, rowBase, colBase, A, Bhi, Blo);
    CP_COMMIT();

    for (int i = 0; i < NCHUNK; i++) {
        if (i + 1 < NCHUNK) { CP_WAIT1(); } else { CP_WAIT0(); }
        __syncthreads();
        if (i + 2 < NCHUNK) {
            gemm_load_stage(sbase, (i + 2) % STAGES, (i + 2) * BKK,
                            tid, rowBase, colBase, A, Bhi, Blo);
            CP_COMMIT();
        }

        const uint32_t st = sbase + (i % STAGES) * STAGE_B;
        #pragma unroll
        for (int ks = 0; ks < 4; ks++) {        // four k16 steps in BK=64
            uint32_t a[2][4], bhi[8][2], blo[8][2];

            // A fragments: lanes 0-15 rows m0-15 chunk ks*2; lanes 16-31 chunk +1
            const int arow0 = warp_m * 32 + (lane & 15);
            const int ac    = ks * 2 + (lane >> 4);
            #pragma unroll
            for (int mt = 0; mt < 2; mt++) {
                const int r = arow0 + mt * 16;
                ldmatrix_x4(a[mt], st + r * 128 + ((ac ^ (r & 7)) * 16));
            }
            // B fragments, paired x4: lanes 0-15 -> nt rows (chunks k0/k8),
            // lanes 16-31 -> nt+1 rows. One x4 yields two n-tiles' fragments.
            const int brow0 = warp_n * 64 + ((lane >> 4) * 8) + (lane & 7);
            const int bc    = ks * 2 + ((lane >> 3) & 1);
            #pragma unroll
            for (int np = 0; np < 4; np++) {    // nt pairs
                const int r = brow0 + np * 16;
                const uint32_t off = r * 128 + ((bc ^ (r & 7)) * 16);
                uint32_t th[4], tl[4];
                ldmatrix_x4(th, st + MTILE_B + off);
                ldmatrix_x4(tl, st + 2 * MTILE_B + off);
                bhi[np * 2][0] = th[0]; bhi[np * 2][1] = th[1];
                bhi[np * 2 + 1][0] = th[2]; bhi[np * 2 + 1][1] = th[3];
                blo[np * 2][0] = tl[0]; blo[np * 2][1] = tl[1];
                blo[np * 2 + 1][0] = tl[2]; blo[np * 2 + 1][1] = tl[3];
            }
            // 2-pass: A*(Bhi+Blo) — exact in B, fp32 accum
            #pragma unroll
            for (int mt = 0; mt < 2; mt++)
                #pragma unroll
                for (int nt = 0; nt < 8; nt++) {
                    mma_16816(acc[mt][nt], a[mt], bhi[nt]);
                    mma_16816(acc[mt][nt], a[mt], blo[nt]);
                }
        }
        __syncthreads();
    }

    // Epilogue: m16n8 acc mapping — c0,c1 row g cols 2q+{0,1}; c2,c3 row g+8.
    const int g = lane >> 2, q = lane & 3;
    #pragma unroll
    for (int mt = 0; mt < 2; mt++) {
        #pragma unroll
        for (int nt = 0; nt < 8; nt++) {
            const int row0 = rowBase + warp_m * 32 + mt * 16 + g;
            const int col  = colBase + warp_n * 64 + nt * 8 + q * 2;
            #pragma unroll
            for (int h = 0; h < 2; h++) {
                const size_t idx = (size_t)(row0 + h * 8) * H_DIM + col;
                float2 add = *reinterpret_cast<const float2*>(addsrc + idx);
                if (MODE == 0) {
                    add.x = fmaxf(add.x, 0.f);
                    add.y = fmaxf(add.y, 0.f);
                }
                float2 o;
                o.x = acc[mt][nt][2 * h + 0] + add.x;
                o.y = acc[mt][nt][2 * h + 1] + add.y;
                *reinterpret_cast<float2*>(C + idx) = o;
            }
        }
    }
}

// ---------------------------------------------------------------------------
// Pipeline:
//   a = fp16(rmsnorm(relu(x), g0));  (bhi,blo) = transpose_split16(w0)
//   r  = a@(bhi+blo) + relu(x)
//   a = fp16(rmsnorm(r, g1));        (bhi,blo) = transpose_split16(w1)
//   r += a@(bhi+blo)            (in place)
//   out = rmsnorm(r, g2)
// ---------------------------------------------------------------------------
extern "C" void kernel_launch(void* const* d_in, const int* in_sizes, int n_in,
                              void* d_out, int out_size) {
    const float* x  = (const float*)d_in[0];
    const float* g0 = (const float*)d_in[1];
    const float* g1 = (const float*)d_in[2];
    const float* g2 = (const float*)d_in[3];
    const float* w0 = (const float*)d_in[4];
    const float* w1 = (const float*)d_in[5];
    float* out = (float*)d_out;

    __half *a = nullptr, *bhi = nullptr, *blo = nullptr;
    float* r = nullptr;
    cudaGetSymbolAddress((void**)&a,   g_a);
    cudaGetSymbolAddress((void**)&bhi, g_bhi);
    cudaGetSymbolAddress((void**)&blo, g_blo);
    cudaGetSymbolAddress((void**)&r,   g_r);

    cudaFuncSetAttribute(gemm_mma_kernel<0>, cudaFuncAttributeMaxDynamicSharedMemorySize, GEMM_SMEM_TOTAL);
    cudaFuncSetAttribute(gemm_mma_kernel<1>, cudaFuncAttributeMaxDynamicSharedMemorySize, GEMM_SMEM_TOTAL);

    dim3 gridN(T_DIM);
    dim3 gridT(H_DIM / 32, H_DIM / 32);
    dim3 gridG(H_DIM / 128, T_DIM / 128);
    dim3 blkT(32, 8);

    rmsnorm_h_kernel<true >  <<<gridN, 256>>>(x, g0, a);
    transpose_split_kernel   <<<gridT, blkT>>>(w0, bhi, blo);
    gemm_mma_kernel<0>       <<<gridG, 256, GEMM_SMEM_TOTAL>>>(a, bhi, blo, x, r);
    rmsnorm_h_kernel<false>  <<<gridN, 256>>>(r, g1, a);
    transpose_split_kernel   <<<gridT, blkT>>>(w1, bhi, blo);
    gemm_mma_kernel<1>       <<<gridG, 256, GEMM_SMEM_TOTAL>>>(a, bhi, blo, r, r);
    rmsnorm_f32_kernel       <<<gridN, 256>>>(r, g2, out);
}

// round 14
// speedup vs baseline: 8.3437x; 2.1302x over previous
#include <cuda_runtime.h>
#include <cuda_fp16.h>
#include <stdint.h>

#define T_DIM 16384
#define H_DIM 4096
#define EPS 1e-5f

// ---------------------------------------------------------------------------
// Scratch (__device__ globals; allocation-free rule)
// ---------------------------------------------------------------------------
__device__ __align__(16) __half g_a [(size_t)T_DIM * H_DIM];  // 128 MB (A fp16)
__device__ __align__(16) float  g_r [(size_t)T_DIM * H_DIM];  // 256 MB
__device__ __align__(16) __half g_b [(size_t)H_DIM * H_DIM];  // 32 MB (B fp16)

// ---------------------------------------------------------------------------
// PTX helpers — family-portable only (ldmatrix / mma.sync / cp.async).
// tcgen05 is rejected by this harness's compute_103 PTX stage (R11 finding).
// ---------------------------------------------------------------------------
__device__ __forceinline__ uint32_t smem_to_u32(const void* p) {
    uint32_t a;
    asm("{ .reg .u64 t; cvta.to.shared.u64 t, %1; cvt.u32.u64 %0, t; }" : "=r"(a) : "l"(p));
    return a;
}
#define CP_ASYNC_16(dst, src) \
    asm volatile("cp.async.cg.shared.global [%0], [%1], 16;" :: "r"(dst), "l"(src))
#define CP_COMMIT() asm volatile("cp.async.commit_group;" ::: "memory")
#define CP_WAIT1()  asm volatile("cp.async.wait_group 1;" ::: "memory")
#define CP_WAIT0()  asm volatile("cp.async.wait_group 0;" ::: "memory")

__device__ __forceinline__ void ldmatrix_x4(uint32_t* r, uint32_t addr) {
    asm volatile("ldmatrix.sync.aligned.m8n8.x4.shared.b16 {%0,%1,%2,%3}, [%4];"
                 : "=r"(r[0]), "=r"(r[1]), "=r"(r[2]), "=r"(r[3]) : "r"(addr));
}
// fp16 MMA, fp32 accumulate
__device__ __forceinline__ void mma_16816(float* c, const uint32_t* a, const uint32_t* b) {
    asm volatile("mma.sync.aligned.m16n8k16.row.col.f32.f16.f16.f32 "
                 "{%0,%1,%2,%3}, {%4,%5,%6,%7}, {%8,%9}, {%0,%1,%2,%3};"
                 : "+f"(c[0]), "+f"(c[1]), "+f"(c[2]), "+f"(c[3])
                 : "r"(a[0]), "r"(a[1]), "r"(a[2]), "r"(a[3]), "r"(b[0]), "r"(b[1]));
}

// ---------------------------------------------------------------------------
// RMSNorm -> fp16 (A operand).
// ---------------------------------------------------------------------------
template<bool RELU_IN>
__global__ void __launch_bounds__(256) rmsnorm_h_kernel(
    const float* __restrict__ in, const float* __restrict__ g,
    __half* __restrict__ oh)
{
    const int row = blockIdx.x;
    const float4* inp = reinterpret_cast<const float4*>(in + (size_t)row * H_DIM);
    const float4* gp  = reinterpret_cast<const float4*>(g);
    uint2* hp = reinterpret_cast<uint2*>(oh + (size_t)row * H_DIM);

    float4 v[4];
    float ssq = 0.f;
    #pragma unroll
    for (int i = 0; i < 4; i++) {
        float4 t = inp[threadIdx.x + i * 256];
        if (RELU_IN) {
            t.x = fmaxf(t.x, 0.f); t.y = fmaxf(t.y, 0.f);
            t.z = fmaxf(t.z, 0.f); t.w = fmaxf(t.w, 0.f);
        }
        v[i] = t;
        ssq += t.x * t.x + t.y * t.y + t.z * t.z + t.w * t.w;
    }

    __shared__ float red[8];
    #pragma unroll
    for (int o = 16; o > 0; o >>= 1) ssq += __shfl_xor_sync(0xffffffffu, ssq, o);
    const int wid = threadIdx.x >> 5, lid = threadIdx.x & 31;
    if (lid == 0) red[wid] = ssq;
    __syncthreads();
    if (wid == 0) {
        float s = (lid < 8) ? red[lid] : 0.f;
        #pragma unroll
        for (int o = 4; o > 0; o >>= 1) s += __shfl_xor_sync(0xffffffffu, s, o);
        if (lid == 0) red[0] = rsqrtf(s * (1.0f / H_DIM) + EPS);
    }
    __syncthreads();
    const float rs = red[0];

    #pragma unroll
    for (int i = 0; i < 4; i++) {
        float4 gg = gp[threadIdx.x + i * 256];
        float4 t = v[i];
        t.x *= rs * gg.x; t.y *= rs * gg.y; t.z *= rs * gg.z; t.w *= rs * gg.w;
        __half h0 = __float2half_rn(t.x), h1 = __float2half_rn(t.y);
        __half h2 = __float2half_rn(t.z), h3 = __float2half_rn(t.w);
        uint2 uh;
        uh.x = (uint32_t)__half_as_ushort(h0) | ((uint32_t)__half_as_ushort(h1) << 16);
        uh.y = (uint32_t)__half_as_ushort(h2) | ((uint32_t)__half_as_ushort(h3) << 16);
        hp[threadIdx.x + i * 256] = uh;
    }
}

// Final RMSNorm -> fp32 out
__global__ void __launch_bounds__(256) rmsnorm_f32_kernel(
    const float* __restrict__ in, const float* __restrict__ g, float* __restrict__ out)
{
    const int row = blockIdx.x;
    const float4* inp  = reinterpret_cast<const float4*>(in + (size_t)row * H_DIM);
    float4*       outp = reinterpret_cast<float4*>(out + (size_t)row * H_DIM);
    const float4* gp   = reinterpret_cast<const float4*>(g);

    float4 v[4];
    float ssq = 0.f;
    #pragma unroll
    for (int i = 0; i < 4; i++) {
        float4 t = inp[threadIdx.x + i * 256];
        v[i] = t;
        ssq += t.x * t.x + t.y * t.y + t.z * t.z + t.w * t.w;
    }
    __shared__ float red[8];
    #pragma unroll
    for (int o = 16; o > 0; o >>= 1) ssq += __shfl_xor_sync(0xffffffffu, ssq, o);
    const int wid = threadIdx.x >> 5, lid = threadIdx.x & 31;
    if (lid == 0) red[wid] = ssq;
    __syncthreads();
    if (wid == 0) {
        float s = (lid < 8) ? red[lid] : 0.f;
        #pragma unroll
        for (int o = 4; o > 0; o >>= 1) s += __shfl_xor_sync(0xffffffffu, s, o);
        if (lid == 0) red[0] = rsqrtf(s * (1.0f / H_DIM) + EPS);
    }
    __syncthreads();
    const float rs = red[0];
    #pragma unroll
    for (int i = 0; i < 4; i++) {
        float4 gg = gp[threadIdx.x + i * 256];
        float4 t = v[i];
        t.x *= rs * gg.x; t.y *= rs * gg.y; t.z *= rs * gg.z; t.w *= rs * gg.w;
        outp[threadIdx.x + i * 256] = t;
    }
}

// ---------------------------------------------------------------------------
// Transpose -> fp16: Bt[n][k] = fp16(w[k][n]).
// ---------------------------------------------------------------------------
__global__ void __launch_bounds__(256) transpose_h_kernel(
    const float* __restrict__ w, __half* __restrict__ b)
{
    __shared__ float tile[32][33];
    const int x  = blockIdx.x * 32 + threadIdx.x;   // n
    const int y0 = blockIdx.y * 32 + threadIdx.y;   // k
    #pragma unroll
    for (int j = 0; j < 4; j++)
        tile[threadIdx.y + 8 * j][threadIdx.x] = w[(size_t)(y0 + 8 * j) * H_DIM + x];
    __syncthreads();
    const int xo = blockIdx.y * 32 + threadIdx.x;   // k
    const int yo = blockIdx.x * 32 + threadIdx.y;   // n
    #pragma unroll
    for (int j = 0; j < 4; j++) {
        float v = tile[threadIdx.x][threadIdx.y + 8 * j];
        b[(size_t)(yo + 8 * j) * H_DIM + xo] = __float2half_rn(v);
    }
}

// ---------------------------------------------------------------------------
// mma.sync fp16 GEMM: C[128x128] = A @ B^T + addend, SINGLE pass.
// Error sources: fp16 rounding of A and B (uncorrelated, ~3.2e-4 aggregate).
//   MODE 0: addend = relu(addsrc);  MODE 1: addend = addsrc (in-place safe)
// 256 threads = 8 warps (4M x 2N), warp tile 32x64, BK=64, 3-stage cp.async.
// Stage = 2 tiles (A, B) x 16 KB = 32 KB; 3 stages = 96 KB -> 2 CTAs/SM.
// Smem rows 128 B, xor-swizzled (chunk16 ^= row&7): conflict-free ldmatrix.
// ---------------------------------------------------------------------------
#define BKK 64
#define NCHUNK (H_DIM / BKK)            // 64
#define MTILE_B 16384                   // 128 rows x 128 B
#define STAGE_B (2 * MTILE_B)           // A, B = 32 KB
#define STAGES 3
#define GEMM_SMEM_TOTAL (STAGES * STAGE_B)  // 96 KB

__device__ __forceinline__ void gemm_load_stage(
    uint32_t sbase, int slot, int k0, int tid, int rowBase, int colBase,
    const __half* A, const __half* B)
{
    const char* gsrc[2];
    gsrc[0] = (const char*)(A + (size_t)rowBase * H_DIM + k0);
    gsrc[1] = (const char*)(B + (size_t)colBase * H_DIM + k0);
    const uint32_t stage_base = sbase + slot * STAGE_B;
    #pragma unroll
    for (int t = 0; t < 2; t++) {
        #pragma unroll
        for (int j = 0; j < 4; j++) {           // 1024 16B chunks / 256 thr
            int idx = j * 256 + tid;
            int r = idx >> 3;                   // tile row 0..127
            int c = idx & 7;                    // 16B chunk 0..7
            const char* src = gsrc[t] + (size_t)r * (H_DIM * 2) + c * 16;
            uint32_t dst = stage_base + t * MTILE_B + r * 128 + ((c ^ (r & 7)) * 16);
            CP_ASYNC_16(dst, src);
        }
    }
}

template<int MODE>
__global__ void __launch_bounds__(256, 2) gemm_mma_kernel(
    const __half* __restrict__ A, const __half* __restrict__ B,
    const float* addsrc, float* C)
{
    extern __shared__ char smem[];
    const uint32_t sbase = smem_to_u32(smem);
    const int tid  = threadIdx.x;
    const int lane = tid & 31;
    const int wid  = tid >> 5;
    const int warp_m = wid & 3;     // 0..3  (M)
    const int warp_n = wid >> 2;    // 0..1  (N)

    const int colBase = blockIdx.x * 128;
    const int rowBase = blockIdx.y * 128;

    float acc[2][8][4];
    #pragma unroll
    for (int mt = 0; mt < 2; mt++)
        #pragma unroll
        for (int nt = 0; nt < 8; nt++)
            #pragma unroll
            for (int q = 0; q < 4; q++) acc[mt][nt][q] = 0.f;

    gemm_load_stage(sbase, 0, 0,   tid, rowBase, colBase, A, B);
    CP_COMMIT();
    gemm_load_stage(sbase, 1, BKK, tid, rowBase, colBase, A, B);
    CP_COMMIT();

    for (int i = 0; i < NCHUNK; i++) {
        if (i + 1 < NCHUNK) { CP_WAIT1(); } else { CP_WAIT0(); }
        __syncthreads();
        if (i + 2 < NCHUNK) {
            gemm_load_stage(sbase, (i + 2) % STAGES, (i + 2) * BKK,
                            tid, rowBase, colBase, A, B);
            CP_COMMIT();
        }

        const uint32_t st = sbase + (i % STAGES) * STAGE_B;
        #pragma unroll
        for (int ks = 0; ks < 4; ks++) {        // four k16 steps in BK=64
            uint32_t a[2][4], b[8][2];

            // A fragments: lanes 0-15 rows m0-15 chunk ks*2; lanes 16-31 +1
            const int arow0 = warp_m * 32 + (lane & 15);
            const int ac    = ks * 2 + (lane >> 4);
            #pragma unroll
            for (int mt = 0; mt < 2; mt++) {
                const int r = arow0 + mt * 16;
                ldmatrix_x4(a[mt], st + r * 128 + ((ac ^ (r & 7)) * 16));
            }
            // B fragments, paired x4: one x4 covers two adjacent n8 tiles.
            const int brow0 = warp_n * 64 + ((lane >> 4) * 8) + (lane & 7);
            const int bc    = ks * 2 + ((lane >> 3) & 1);
            #pragma unroll
            for (int np = 0; np < 4; np++) {
                const int r = brow0 + np * 16;
                uint32_t tb[4];
                ldmatrix_x4(tb, st + MTILE_B + r * 128 + ((bc ^ (r & 7)) * 16));
                b[np * 2][0] = tb[0]; b[np * 2][1] = tb[1];
                b[np * 2 + 1][0] = tb[2]; b[np * 2 + 1][1] = tb[3];
            }
            // single-pass fp16 MMA, fp32 accum
            #pragma unroll
            for (int mt = 0; mt < 2; mt++)
                #pragma unroll
                for (int nt = 0; nt < 8; nt++)
                    mma_16816(acc[mt][nt], a[mt], b[nt]);
        }
        __syncthreads();
    }

    // Epilogue: m16n8 acc mapping — c0,c1 row g cols 2q+{0,1}; c2,c3 row g+8.
    const int g = lane >> 2, q = lane & 3;
    #pragma unroll
    for (int mt = 0; mt < 2; mt++) {
        #pragma unroll
        for (int nt = 0; nt < 8; nt++) {
            const int row0 = rowBase + warp_m * 32 + mt * 16 + g;
            const int col  = colBase + warp_n * 64 + nt * 8 + q * 2;
            #pragma unroll
            for (int h = 0; h < 2; h++) {
                const size_t idx = (size_t)(row0 + h * 8) * H_DIM + col;
                float2 add = *reinterpret_cast<const float2*>(addsrc + idx);
                if (MODE == 0) {
                    add.x = fmaxf(add.x, 0.f);
                    add.y = fmaxf(add.y, 0.f);
                }
                float2 o;
                o.x = acc[mt][nt][2 * h + 0] + add.x;
                o.y = acc[mt][nt][2 * h + 1] + add.y;
                *reinterpret_cast<float2*>(C + idx) = o;
            }
        }
    }
}

// ---------------------------------------------------------------------------
// Pipeline:
//   a = fp16(rmsnorm(relu(x), g0));  b = fp16(w0^T)
//   r  = a@b^T + relu(x)
//   a = fp16(rmsnorm(r, g1));        b = fp16(w1^T)
//   r += a@b^T              (in place)
//   out = rmsnorm(r, g2)
// ---------------------------------------------------------------------------
extern "C" void kernel_launch(void* const* d_in, const int* in_sizes, int n_in,
                              void* d_out, int out_size) {
    const float* x  = (const float*)d_in[0];
    const float* g0 = (const float*)d_in[1];
    const float* g1 = (const float*)d_in[2];
    const float* g2 = (const float*)d_in[3];
    const float* w0 = (const float*)d_in[4];
    const float* w1 = (const float*)d_in[5];
    float* out = (float*)d_out;

    __half *a = nullptr, *b = nullptr;
    float* r = nullptr;
    cudaGetSymbolAddress((void**)&a, g_a);
    cudaGetSymbolAddress((void**)&b, g_b);
    cudaGetSymbolAddress((void**)&r, g_r);

    cudaFuncSetAttribute(gemm_mma_kernel<0>, cudaFuncAttributeMaxDynamicSharedMemorySize, GEMM_SMEM_TOTAL);
    cudaFuncSetAttribute(gemm_mma_kernel<1>, cudaFuncAttributeMaxDynamicSharedMemorySize, GEMM_SMEM_TOTAL);

    dim3 gridN(T_DIM);
    dim3 gridT(H_DIM / 32, H_DIM / 32);
    dim3 gridG(H_DIM / 128, T_DIM / 128);
    dim3 blkT(32, 8);

    rmsnorm_h_kernel<true >  <<<gridN, 256>>>(x, g0, a);
    transpose_h_kernel       <<<gridT, blkT>>>(w0, b);
    gemm_mma_kernel<0>       <<<gridG, 256, GEMM_SMEM_TOTAL>>>(a, b, x, r);
    rmsnorm_h_kernel<false>  <<<gridN, 256>>>(r, g1, a);
    transpose_h_kernel       <<<gridT, blkT>>>(w1, b);
    gemm_mma_kernel<1>       <<<gridG, 256, GEMM_SMEM_TOTAL>>>(a, b, r, r);
    rmsnorm_f32_kernel       <<<gridN, 256>>>(r, g2, out);
}